// round 11
// baseline (speedup 1.0000x reference)
#include <cuda_runtime.h>
#include <cuda_fp16.h>
#include <math.h>
#include <stdint.h>

#define D      256
#define KNBR   32
#define TOPK   16
#define MAXN   20096      // 157 * 128, padded
#define K2     512        // GEMM K = 2*D

// ---------------- scratch (__device__ globals; zero-init, no allocs) -------
__device__ __align__(128) __half g_Ah[(size_t)MAXN * K2];  // [row, 512] fp16
__device__ __align__(128) __half g_Bh[D * K2];             // [n, 512] fp16 (W^T)
__device__ float g_vs[D];
__device__ float g_vn[D];
// prep->phase1 handshake (self-resetting; zero-init at load)
__device__ unsigned g_flagv;        // prep GEMV blocks done (target 16)
__device__ unsigned g_fcons;        // phase1 blocks past the wait

__device__ __forceinline__ uint32_t smem_u32(const void* p) {
    uint32_t a;
    asm("{ .reg .u64 t; cvta.to.shared.u64 t, %1; cvt.u32.u64 %0, t; }" : "=r"(a) : "l"(p));
    return a;
}
__device__ __forceinline__ void pdl_trigger() {
    asm volatile("griddepcontrol.launch_dependents;");
}
__device__ __forceinline__ unsigned acq_ld(const unsigned* p) {
    unsigned v;
    asm volatile("ld.acquire.gpu.global.u32 %0, [%1];" : "=r"(v) : "l"(p));
    return v;
}

// ---------------------------------------------------------------------------
// prep: blocks 0..15 -> v = W @ a GEMV (signal g_flagv);
//       blocks 16..47 -> convB via 64x64 tiled transpose (coalesced both ways)
// ---------------------------------------------------------------------------
__global__ void __launch_bounds__(256)
prep_kernel(const float* __restrict__ sw, const float* __restrict__ nw,
            const float* __restrict__ attn)
{
    pdl_trigger();                                   // let phase1 launch now
    const int b = blockIdx.x;
    const int t = threadIdx.x;

    if (b < 16) {
        __shared__ float a[D];
        const int wid = t >> 5, lane = t & 31;
        a[t] = attn[t];
        __syncthreads();

        const float* w = ((b & 1) == 0) ? sw : nw;
#pragma unroll
        for (int r = 0; r < 4; r++) {
            int row = (b >> 1) * 32 + wid * 4 + r;
            const float4* wr = (const float4*)(w + (size_t)row * D);
            float4 v0 = wr[lane], v1 = wr[lane + 32];
            float p = v0.x * a[4 * lane + 0] + v0.y * a[4 * lane + 1]
                    + v0.z * a[4 * lane + 2] + v0.w * a[4 * lane + 3]
                    + v1.x * a[128 + 4 * lane + 0] + v1.y * a[128 + 4 * lane + 1]
                    + v1.z * a[128 + 4 * lane + 2] + v1.w * a[128 + 4 * lane + 3];
#pragma unroll
            for (int o = 16; o > 0; o >>= 1) p += __shfl_down_sync(0xffffffffu, p, o);
            if (lane == 0) { if ((b & 1) == 0) g_vs[row] = p; else g_vn[row] = p; }
        }
        __syncthreads();
        if (t == 0) { __threadfence(); atomicAdd(&g_flagv, 1u); }
    } else {
        // convB tile: tid selects 64k x 64n tile; transpose through padded SMEM
        __shared__ float tsm[64][65];
        const int tid = b - 16;                  // 0..31
        const int k0  = (tid & 7) * 64;          // 0..448
        const int n0  = (tid >> 3) * 64;         // 0..192
        const float* w = (k0 < D) ? sw : nw;
        const int kb = (k0 < D) ? k0 : (k0 - D);

        // read: rows of W (coalesced in n)
#pragma unroll
        for (int i = 0; i < 16; i++) {
            int idx = t + i * 256;               // 0..4095
            int kk = idx >> 6, nn = idx & 63;
            tsm[kk][nn] = w[(size_t)(kb + kk) * D + n0 + nn];
        }
        __syncthreads();
        // write: rows of B^T (coalesced in k)
#pragma unroll
        for (int i = 0; i < 16; i++) {
            int idx = t + i * 256;
            int nn = idx >> 6, kk = idx & 63;
            g_Bh[(size_t)(n0 + nn) * K2 + k0 + kk] = __float2half_rn(tsm[kk][nn]);
        }
    }
}

// ---------------------------------------------------------------------------
// Phase 1: per node — logits, softmax over 33, top-16, weighted neighbor sum.
// PDL secondary of prep: does prep-independent work first, then a short spin
// on g_flagv. Writes A fp16.
// ---------------------------------------------------------------------------
__global__ void __launch_bounds__(256)
phase1_kernel(const float* __restrict__ self_vecs,
              const float* __restrict__ neigh_vecs)
{
    __shared__ float4 tile[KNBR * D / 4];   // 32 KB
    __shared__ float4 vn4[D / 4];
    __shared__ float  dots[KNBR];
    __shared__ float  warp_part[8];
    __shared__ float  s_selflogit;
    __shared__ float  sel_w[TOPK];
    __shared__ int    sel_i[TOPK];

    const int n    = blockIdx.x;
    const int t    = threadIdx.x;
    const int wid  = t >> 5;
    const int lane = t & 31;

    // independent of prep: stream the 32x256 neighbor tile
    const float4* src = (const float4*)(neigh_vecs + (size_t)n * KNBR * D);
#pragma unroll
    for (int i = 0; i < 8; i++) {
        uint32_t dst = smem_u32(&tile[t + 256 * i]);
        asm volatile("cp.async.cg.shared.global [%0], [%1], 16;"
                     :: "r"(dst), "l"((const void*)(src + t + 256 * i)));
    }
    asm volatile("cp.async.commit_group;");

    // independent of prep: self row load + fp16 write (A cols 0..255)
    float sv = self_vecs[(size_t)n * D + t];
    g_Ah[(size_t)n * K2 + t] = __float2half_rn(sv);

    // wait for prep's GEMV results (g_vs / g_vn); self-reset by last consumer
    if (t == 0) {
        while (acq_ld(&g_flagv) < 16u) __nanosleep(64);
        unsigned of = atomicAdd(&g_fcons, 1u);
        if (of == (unsigned)(gridDim.x - 1)) {
            g_flagv = 0u; g_fcons = 0u;
            __threadfence();
        }
    }
    __syncthreads();

    if (t < D / 4) vn4[t] = ((const float4*)g_vn)[t];

    float sp = sv * g_vs[t];
#pragma unroll
    for (int o = 16; o > 0; o >>= 1) sp += __shfl_down_sync(0xffffffffu, sp, o);
    if (lane == 0) warp_part[wid] = sp;

    asm volatile("cp.async.wait_group 0;");
    __syncthreads();

#pragma unroll
    for (int r = 0; r < 4; r++) {
        int row = wid * 4 + r;
        float4 a0 = tile[row * 64 + lane];
        float4 a1 = tile[row * 64 + 32 + lane];
        float4 b0 = vn4[lane];
        float4 b1 = vn4[32 + lane];
        float p = a0.x * b0.x + a0.y * b0.y + a0.z * b0.z + a0.w * b0.w
                + a1.x * b1.x + a1.y * b1.y + a1.z * b1.z + a1.w * b1.w;
#pragma unroll
        for (int o = 16; o > 0; o >>= 1) p += __shfl_down_sync(0xffffffffu, p, o);
        if (lane == 0) dots[row] = p;
    }
    if (t == 0) {
        float s = 0.f;
#pragma unroll
        for (int i = 0; i < 8; i++) s += warp_part[i];
        s_selflogit = s;
    }
    __syncthreads();

    if (wid == 0) {
        float l  = fmaxf(dots[lane], 0.f);
        float l0 = fmaxf(s_selflogit, 0.f);
        float m = l;
#pragma unroll
        for (int o = 16; o > 0; o >>= 1) m = fmaxf(m, __shfl_xor_sync(0xffffffffu, m, o));
        m = fmaxf(m, l0);
        float e = expf(l - m);
        float ssum = e;
#pragma unroll
        for (int o = 16; o > 0; o >>= 1) ssum += __shfl_xor_sync(0xffffffffu, ssum, o);
        float denom = ssum + expf(l0 - m);
        float score = e / denom;

        int rank = 0;
#pragma unroll
        for (int j = 0; j < KNBR; j++) {
            float sj = __shfl_sync(0xffffffffu, score, j);
            rank += (sj > score) || (sj == score && j < lane);
        }
        if (rank < TOPK) { sel_w[rank] = score; sel_i[rank] = lane; }
    }
    __syncthreads();

    const float* ts = (const float*)tile;
    float acc = 0.f;
#pragma unroll
    for (int i = 0; i < TOPK; i++) acc += sel_w[i] * ts[sel_i[i] * D + t];
    g_Ah[(size_t)n * K2 + D + t] = __float2half_rn(acc);
}

// ---------------------------------------------------------------------------
// Phase 2: out = relu(A @ B^T), single-pass fp16, fp32 accum.
// BM=128, BN=128, BK=64, 8 warps (64x32 warp tiles), 3-stage cp.async.
// Plain stream-ordered launch (NO overlap with phase1 — proven harmful).
// ---------------------------------------------------------------------------
#define BK    64
#define STG   36864                    // stage bytes: A 18432 + B 18432
#define AOF   0
#define B0OF  18432
#define GEMM_SMEM (3 * STG)            // 110592
#define NIT   8

__global__ void __launch_bounds__(256)
gemm_kernel(float* __restrict__ out, int nrows)
{
    extern __shared__ uint8_t sm[];
    const uint32_t smb = smem_u32(sm);

    const int t    = threadIdx.x;
    const int wid  = t >> 5;
    const int lane = t & 31;
    const int row0 = blockIdx.x * 128;
    const int col0 = blockIdx.y * 128;
    const int wm   = (wid >> 2) * 64;    // 0/64
    const int wn   = (wid & 3) * 32;     // 0/32/64/96

    uint32_t offA[4];
#pragma unroll
    for (int i = 0; i < 4; i++)
        offA[i] = AOF + (uint32_t)(wm + i * 16 + (lane & 15)) * 144
                + (uint32_t)(((lane >> 4) << 3) * 2);
    uint32_t offB[2];
#pragma unroll
    for (int p = 0; p < 2; p++)
        offB[p] = (uint32_t)(wn + (2 * p + ((lane >> 3) >> 1)) * 8 + (lane & 7)) * 144
                + (uint32_t)(((lane >> 3) & 1) * 16);

    float acc[4][4][4];
#pragma unroll
    for (int i = 0; i < 4; i++)
#pragma unroll
        for (int j = 0; j < 4; j++)
#pragma unroll
            for (int q = 0; q < 4; q++) acc[i][j][q] = 0.f;

    auto prefetch = [&](int jt, int st) {
        const int koff = jt * BK;
        uint8_t* stage = sm + st * STG;
#pragma unroll
        for (int i = 0; i < 4; i++) {
            int idx = t + i * 256;
            int r = idx >> 3, c = idx & 7;
            uint32_t da = smem_u32(stage + AOF + r * 144 + c * 16);
            const void* sa = g_Ah + (size_t)(row0 + r) * K2 + koff + c * 8;
            asm volatile("cp.async.cg.shared.global [%0], [%1], 16;" :: "r"(da), "l"(sa));
        }
#pragma unroll
        for (int i = 0; i < 4; i++) {
            int idx = t + i * 256;
            int r = idx >> 3, c = idx & 7;
            uint32_t db = smem_u32(stage + B0OF + r * 144 + c * 16);
            const void* sb = g_Bh + (size_t)(col0 + r) * K2 + koff + c * 8;
            asm volatile("cp.async.cg.shared.global [%0], [%1], 16;" :: "r"(db), "l"(sb));
        }
        asm volatile("cp.async.commit_group;");
    };

    prefetch(0, 0);
    prefetch(1, 1);

#pragma unroll 1
    for (int it = 0; it < NIT; it++) {
        asm volatile("cp.async.wait_group 1;");
        __syncthreads();                 // it-1 compute done before stage reuse below

        if (it + 2 < NIT) prefetch(it + 2, (it + 2) % 3);
        else asm volatile("cp.async.commit_group;");

        const uint32_t stage = smb + (uint32_t)((it % 3) * STG);

#pragma unroll
        for (int s = 0; s < 4; s++) {    // four k16 steps in BK=64
            const uint32_t sk = stage + (uint32_t)(s * 32);
            uint32_t a[4][4], b[4][2];
#pragma unroll
            for (int i = 0; i < 4; i++) {
                asm volatile("ldmatrix.sync.aligned.m8n8.x4.shared.b16 {%0,%1,%2,%3}, [%4];"
                             : "=r"(a[i][0]), "=r"(a[i][1]), "=r"(a[i][2]), "=r"(a[i][3])
                             : "r"(sk + offA[i]));
            }
#pragma unroll
            for (int p = 0; p < 2; p++) {
                asm volatile("ldmatrix.sync.aligned.m8n8.x4.shared.b16 {%0,%1,%2,%3}, [%4];"
                             : "=r"(b[2 * p][0]), "=r"(b[2 * p][1]),
                               "=r"(b[2 * p + 1][0]), "=r"(b[2 * p + 1][1])
                             : "r"(sk + B0OF + offB[p]));
            }
#pragma unroll
            for (int i = 0; i < 4; i++)
#pragma unroll
                for (int j = 0; j < 4; j++) {
                    asm volatile(
                        "mma.sync.aligned.m16n8k16.row.col.f32.f16.f16.f32 "
                        "{%0,%1,%2,%3}, {%4,%5,%6,%7}, {%8,%9}, {%0,%1,%2,%3};"
                        : "+f"(acc[i][j][0]), "+f"(acc[i][j][1]),
                          "+f"(acc[i][j][2]), "+f"(acc[i][j][3])
                        : "r"(a[i][0]), "r"(a[i][1]), "r"(a[i][2]), "r"(a[i][3]),
                          "r"(b[j][0]), "r"(b[j][1]));
                }
        }
    }

    __syncthreads();

    // epilogue: relu + store
#pragma unroll
    for (int i = 0; i < 4; i++) {
        int rA = row0 + wm + i * 16 + (lane >> 2);
        int rB = rA + 8;
#pragma unroll
        for (int j = 0; j < 4; j++) {
            int c = col0 + wn + j * 8 + (lane & 3) * 2;
            if (rA < nrows) {
                float2 v;
                v.x = fmaxf(acc[i][j][0], 0.f);
                v.y = fmaxf(acc[i][j][1], 0.f);
                *(float2*)&out[(size_t)rA * D + c] = v;
            }
            if (rB < nrows) {
                float2 v;
                v.x = fmaxf(acc[i][j][2], 0.f);
                v.y = fmaxf(acc[i][j][3], 0.f);
                *(float2*)&out[(size_t)rB * D + c] = v;
            }
        }
    }
}

// ---------------------------------------------------------------------------
extern "C" void kernel_launch(void* const* d_in, const int* in_sizes, int n_in,
                              void* d_out, int out_size)
{
    const float* self_vecs = (const float*)d_in[0];
    const float* neigh     = (const float*)d_in[1];
    const float* sw        = (const float*)d_in[2];
    const float* nw        = (const float*)d_in[3];
    const float* attn      = (const float*)d_in[4];
    float* out             = (float*)d_out;

    const int nrows = in_sizes[0] / D;   // 20000

    prep_kernel<<<48, 256>>>(sw, nw, attn);

    {   // phase1: PDL secondary of prep (the only overlap kept)
        cudaLaunchAttribute at[1];
        at[0].id = cudaLaunchAttributeProgrammaticStreamSerialization;
        at[0].val.programmaticStreamSerializationAllowed = 1;
        cudaLaunchConfig_t cfg = {};
        cfg.gridDim = dim3((unsigned)nrows, 1, 1);
        cfg.blockDim = dim3(256, 1, 1);
        cfg.dynamicSmemBytes = 0;
        cfg.stream = 0;
        cfg.attrs = at;
        cfg.numAttrs = 1;
        cudaLaunchKernelEx(&cfg, phase1_kernel, self_vecs, neigh);
    }

    cudaFuncSetAttribute(gemm_kernel, cudaFuncAttributeMaxDynamicSharedMemorySize, GEMM_SMEM);
    dim3 g2((nrows + 127) / 128, 2);
    gemm_kernel<<<g2, 256, GEMM_SMEM>>>(out, nrows);
}

// round 12
// speedup vs baseline: 1.1767x; 1.1767x over previous
#include <cuda_runtime.h>
#include <cuda_fp16.h>
#include <math.h>
#include <stdint.h>

#define D      256
#define KNBR   32
#define TOPK   16
#define MAXN   20096      // 157 * 128, padded
#define K2     512        // GEMM K = 2*D

// ---------------- scratch (__device__ globals; zero-init, no allocs) -------
__device__ __align__(128) __half g_Ah[(size_t)MAXN * K2];  // [row, 512] fp16
__device__ __align__(128) __half g_Bh[D * K2];             // [n, 512] fp16 (W^T)
__device__ float g_vs[D];
__device__ float g_vn[D];

__device__ __forceinline__ uint32_t smem_u32(const void* p) {
    uint32_t a;
    asm("{ .reg .u64 t; cvta.to.shared.u64 t, %1; cvt.u32.u64 %0, t; }" : "=r"(a) : "l"(p));
    return a;
}

// ---------------------------------------------------------------------------
// prep (exact R9 form): blocks 0..15 GEMV; blocks 16..527 convB fp16 scatter.
// ---------------------------------------------------------------------------
__global__ void __launch_bounds__(256)
prep_kernel(const float* __restrict__ sw, const float* __restrict__ nw,
            const float* __restrict__ attn)
{
    const int b = blockIdx.x;
    const int t = threadIdx.x;

    if (b < 16) {
        __shared__ float a[D];
        const int wid = t >> 5, lane = t & 31;
        a[t] = attn[t];
        __syncthreads();

        const float* w = ((b & 1) == 0) ? sw : nw;
#pragma unroll
        for (int r = 0; r < 4; r++) {
            int row = (b >> 1) * 32 + wid * 4 + r;
            const float4* wr = (const float4*)(w + (size_t)row * D);
            float4 v0 = wr[lane], v1 = wr[lane + 32];
            float p = v0.x * a[4 * lane + 0] + v0.y * a[4 * lane + 1]
                    + v0.z * a[4 * lane + 2] + v0.w * a[4 * lane + 3]
                    + v1.x * a[128 + 4 * lane + 0] + v1.y * a[128 + 4 * lane + 1]
                    + v1.z * a[128 + 4 * lane + 2] + v1.w * a[128 + 4 * lane + 3];
#pragma unroll
            for (int o = 16; o > 0; o >>= 1) p += __shfl_down_sync(0xffffffffu, p, o);
            if (lane == 0) { if ((b & 1) == 0) g_vs[row] = p; else g_vn[row] = p; }
        }
    } else {
        int idx = (b - 16) * 256 + t;                // 0 .. 131071
        int n = idx & 255;
        int k = idx >> 8;                            // 0 .. 511
        float w = (k < D) ? sw[(size_t)k * D + n] : nw[(size_t)(k - D) * D + n];
        g_Bh[(size_t)n * K2 + k] = __float2half_rn(w);
    }
}

// ---------------------------------------------------------------------------
// Phase 1: 4 nodes per block, double-buffered tiles. Per node: logits,
// softmax over 33, top-16, weighted sum; writes A fp16.
// SMEM layout (dynamic, 66048 B): tile0 @0, tile1 @32768, ctrl @65536.
// ---------------------------------------------------------------------------
#define P1_SMEM 66048

__global__ void __launch_bounds__(256)
phase1_kernel(const float* __restrict__ self_vecs,
              const float* __restrict__ neigh_vecs, int nrows)
{
    extern __shared__ uint8_t sm[];
    float4* tiles[2] = { (float4*)sm, (float4*)(sm + 32768) };
    float*  dots  = (float*)(sm + 65536);     // [32]
    float*  wpart = (float*)(sm + 65664);     // [32] : q*8 + wid
    float*  slog  = (float*)(sm + 65792);     // [1]
    float*  sel_w = (float*)(sm + 65808);     // [16]
    int*    sel_i = (int*)(sm + 65872);       // [16]

    const int n0   = blockIdx.x * 4;
    const int t    = threadIdx.x;
    const int wid  = t >> 5;
    const int lane = t & 31;

    // issue tiles for nodes n0+0, n0+1 (one commit group each)
#pragma unroll
    for (int q = 0; q < 2; q++) {
        int nn = n0 + q; if (nn >= nrows) nn = nrows - 1;
        const float4* src = (const float4*)(neigh_vecs + (size_t)nn * KNBR * D);
        float4* dstb = tiles[q];
#pragma unroll
        for (int i = 0; i < 8; i++) {
            uint32_t dst = smem_u32(&dstb[t + 256 * i]);
            asm volatile("cp.async.cg.shared.global [%0], [%1], 16;"
                         :: "r"(dst), "l"((const void*)(src + t + 256 * i)));
        }
        asm volatile("cp.async.commit_group;");
    }

    // upfront: self rows of all 4 nodes (independent of tiles)
    const float vs_t = g_vs[t];
#pragma unroll
    for (int q = 0; q < 4; q++) {
        int n = n0 + q;
        int nn = (n < nrows) ? n : (nrows - 1);
        float sv = self_vecs[(size_t)nn * D + t];
        if (n < nrows) g_Ah[(size_t)n * K2 + t] = __float2half_rn(sv);
        float sp = sv * vs_t;
#pragma unroll
        for (int o = 16; o > 0; o >>= 1) sp += __shfl_down_sync(0xffffffffu, sp, o);
        if (lane == 0) wpart[q * 8 + wid] = sp;
    }

    // v_neigh fragments in registers (each lane's two float4s)
    const float4 vb0 = ((const float4*)g_vn)[lane];
    const float4 vb1 = ((const float4*)g_vn)[32 + lane];

#pragma unroll 1
    for (int q = 0; q < 4; q++) {
        const int n = n0 + q;
        if (q < 3) asm volatile("cp.async.wait_group 1;");
        else       asm volatile("cp.async.wait_group 0;");
        __syncthreads();                         // tile q ready for all threads

        const float4* tile = tiles[q & 1];

        // neighbor dots: warp w handles rows 4w..4w+3
#pragma unroll
        for (int r = 0; r < 4; r++) {
            int row = wid * 4 + r;
            float4 a0 = tile[row * 64 + lane];
            float4 a1 = tile[row * 64 + 32 + lane];
            float p = a0.x * vb0.x + a0.y * vb0.y + a0.z * vb0.z + a0.w * vb0.w
                    + a1.x * vb1.x + a1.y * vb1.y + a1.z * vb1.z + a1.w * vb1.w;
#pragma unroll
            for (int o = 16; o > 0; o >>= 1) p += __shfl_down_sync(0xffffffffu, p, o);
            if (lane == 0) dots[row] = p;
        }
        if (t == 0) {
            float s = 0.f;
#pragma unroll
            for (int i = 0; i < 8; i++) s += wpart[q * 8 + i];
            *slog = s;
        }
        __syncthreads();

        if (wid == 0) {
            float l  = fmaxf(dots[lane], 0.f);
            float l0 = fmaxf(*slog, 0.f);
            float m = l;
#pragma unroll
            for (int o = 16; o > 0; o >>= 1) m = fmaxf(m, __shfl_xor_sync(0xffffffffu, m, o));
            m = fmaxf(m, l0);
            float e = expf(l - m);
            float ssum = e;
#pragma unroll
            for (int o = 16; o > 0; o >>= 1) ssum += __shfl_xor_sync(0xffffffffu, ssum, o);
            float denom = ssum + expf(l0 - m);
            float score = e / denom;

            int rank = 0;
#pragma unroll
            for (int j = 0; j < KNBR; j++) {
                float sj = __shfl_sync(0xffffffffu, score, j);
                rank += (sj > score) || (sj == score && j < lane);
            }
            if (rank < TOPK) { sel_w[rank] = score; sel_i[rank] = lane; }
        }
        __syncthreads();

        // weighted sum of selected rows, element d = t
        const float* ts = (const float*)tile;
        float acc = 0.f;
#pragma unroll
        for (int i = 0; i < TOPK; i++) acc += sel_w[i] * ts[sel_i[i] * D + t];
        if (n < nrows) g_Ah[(size_t)n * K2 + D + t] = __float2half_rn(acc);

        // re-issue this buffer with tile q+2 (after all readers are done)
        if (q < 2) {
            __syncthreads();
            int nn = n0 + q + 2; if (nn >= nrows) nn = nrows - 1;
            const float4* src = (const float4*)(neigh_vecs + (size_t)nn * KNBR * D);
            float4* dstb = tiles[q & 1];
#pragma unroll
            for (int i = 0; i < 8; i++) {
                uint32_t dst = smem_u32(&dstb[t + 256 * i]);
                asm volatile("cp.async.cg.shared.global [%0], [%1], 16;"
                             :: "r"(dst), "l"((const void*)(src + t + 256 * i)));
            }
            asm volatile("cp.async.commit_group;");
        }
    }
}

// ---------------------------------------------------------------------------
// Phase 2 (exact R9 form): out = relu(A @ B^T), single-pass fp16, fp32 accum.
// BM=128, BN=128, BK=64, 8 warps (64x32 warp tiles), 3-stage cp.async.
// ---------------------------------------------------------------------------
#define BK    64
#define STG   36864                    // stage bytes: A 18432 + B 18432
#define AOF   0
#define B0OF  18432
#define GEMM_SMEM (3 * STG)            // 110592
#define NIT   8

__global__ void __launch_bounds__(256)
gemm_kernel(float* __restrict__ out, int nrows)
{
    extern __shared__ uint8_t sm[];
    const uint32_t smb = smem_u32(sm);

    const int t    = threadIdx.x;
    const int wid  = t >> 5;
    const int lane = t & 31;
    const int row0 = blockIdx.x * 128;
    const int col0 = blockIdx.y * 128;
    const int wm   = (wid >> 2) * 64;    // 0/64
    const int wn   = (wid & 3) * 32;     // 0/32/64/96

    uint32_t offA[4];
#pragma unroll
    for (int i = 0; i < 4; i++)
        offA[i] = AOF + (uint32_t)(wm + i * 16 + (lane & 15)) * 144
                + (uint32_t)(((lane >> 4) << 3) * 2);
    uint32_t offB[2];
#pragma unroll
    for (int p = 0; p < 2; p++)
        offB[p] = (uint32_t)(wn + (2 * p + ((lane >> 3) >> 1)) * 8 + (lane & 7)) * 144
                + (uint32_t)(((lane >> 3) & 1) * 16);

    float acc[4][4][4];
#pragma unroll
    for (int i = 0; i < 4; i++)
#pragma unroll
        for (int j = 0; j < 4; j++)
#pragma unroll
            for (int q = 0; q < 4; q++) acc[i][j][q] = 0.f;

    auto prefetch = [&](int jt, int st) {
        const int koff = jt * BK;
        uint8_t* stage = sm + st * STG;
#pragma unroll
        for (int i = 0; i < 4; i++) {
            int idx = t + i * 256;
            int r = idx >> 3, c = idx & 7;
            uint32_t da = smem_u32(stage + AOF + r * 144 + c * 16);
            const void* sa = g_Ah + (size_t)(row0 + r) * K2 + koff + c * 8;
            asm volatile("cp.async.cg.shared.global [%0], [%1], 16;" :: "r"(da), "l"(sa));
        }
#pragma unroll
        for (int i = 0; i < 4; i++) {
            int idx = t + i * 256;
            int r = idx >> 3, c = idx & 7;
            uint32_t db = smem_u32(stage + B0OF + r * 144 + c * 16);
            const void* sb = g_Bh + (size_t)(col0 + r) * K2 + koff + c * 8;
            asm volatile("cp.async.cg.shared.global [%0], [%1], 16;" :: "r"(db), "l"(sb));
        }
        asm volatile("cp.async.commit_group;");
    };

    prefetch(0, 0);
    prefetch(1, 1);

#pragma unroll 1
    for (int it = 0; it < NIT; it++) {
        asm volatile("cp.async.wait_group 1;");
        __syncthreads();                 // it-1 compute done before stage reuse below

        if (it + 2 < NIT) prefetch(it + 2, (it + 2) % 3);
        else asm volatile("cp.async.commit_group;");

        const uint32_t stage = smb + (uint32_t)((it % 3) * STG);

#pragma unroll
        for (int s = 0; s < 4; s++) {    // four k16 steps in BK=64
            const uint32_t sk = stage + (uint32_t)(s * 32);
            uint32_t a[4][4], b[4][2];
#pragma unroll
            for (int i = 0; i < 4; i++) {
                asm volatile("ldmatrix.sync.aligned.m8n8.x4.shared.b16 {%0,%1,%2,%3}, [%4];"
                             : "=r"(a[i][0]), "=r"(a[i][1]), "=r"(a[i][2]), "=r"(a[i][3])
                             : "r"(sk + offA[i]));
            }
#pragma unroll
            for (int p = 0; p < 2; p++) {
                asm volatile("ldmatrix.sync.aligned.m8n8.x4.shared.b16 {%0,%1,%2,%3}, [%4];"
                             : "=r"(b[2 * p][0]), "=r"(b[2 * p][1]),
                               "=r"(b[2 * p + 1][0]), "=r"(b[2 * p + 1][1])
                             : "r"(sk + B0OF + offB[p]));
            }
#pragma unroll
            for (int i = 0; i < 4; i++)
#pragma unroll
                for (int j = 0; j < 4; j++) {
                    asm volatile(
                        "mma.sync.aligned.m16n8k16.row.col.f32.f16.f16.f32 "
                        "{%0,%1,%2,%3}, {%4,%5,%6,%7}, {%8,%9}, {%0,%1,%2,%3};"
                        : "+f"(acc[i][j][0]), "+f"(acc[i][j][1]),
                          "+f"(acc[i][j][2]), "+f"(acc[i][j][3])
                        : "r"(a[i][0]), "r"(a[i][1]), "r"(a[i][2]), "r"(a[i][3]),
                          "r"(b[j][0]), "r"(b[j][1]));
                }
        }
    }

    __syncthreads();

    // epilogue: relu + store
#pragma unroll
    for (int i = 0; i < 4; i++) {
        int rA = row0 + wm + i * 16 + (lane >> 2);
        int rB = rA + 8;
#pragma unroll
        for (int j = 0; j < 4; j++) {
            int c = col0 + wn + j * 8 + (lane & 3) * 2;
            if (rA < nrows) {
                float2 v;
                v.x = fmaxf(acc[i][j][0], 0.f);
                v.y = fmaxf(acc[i][j][1], 0.f);
                *(float2*)&out[(size_t)rA * D + c] = v;
            }
            if (rB < nrows) {
                float2 v;
                v.x = fmaxf(acc[i][j][2], 0.f);
                v.y = fmaxf(acc[i][j][3], 0.f);
                *(float2*)&out[(size_t)rB * D + c] = v;
            }
        }
    }
}

// ---------------------------------------------------------------------------
extern "C" void kernel_launch(void* const* d_in, const int* in_sizes, int n_in,
                              void* d_out, int out_size)
{
    const float* self_vecs = (const float*)d_in[0];
    const float* neigh     = (const float*)d_in[1];
    const float* sw        = (const float*)d_in[2];
    const float* nw        = (const float*)d_in[3];
    const float* attn      = (const float*)d_in[4];
    float* out             = (float*)d_out;

    const int nrows = in_sizes[0] / D;   // 20000

    prep_kernel<<<16 + (D * K2) / 256, 256>>>(sw, nw, attn);

    cudaFuncSetAttribute(phase1_kernel, cudaFuncAttributeMaxDynamicSharedMemorySize, P1_SMEM);
    phase1_kernel<<<(nrows + 3) / 4, 256, P1_SMEM>>>(self_vecs, neigh, nrows);

    cudaFuncSetAttribute(gemm_kernel, cudaFuncAttributeMaxDynamicSharedMemorySize, GEMM_SMEM);
    dim3 g2((nrows + 127) / 128, 2);
    gemm_kernel<<<g2, 256, GEMM_SMEM>>>(out, nrows);
}

// round 13
// speedup vs baseline: 1.4547x; 1.2363x over previous
#include <cuda_runtime.h>
#include <cuda_fp16.h>
#include <math.h>
#include <stdint.h>

#define D      256
#define KNBR   32
#define TOPK   16
#define MAXN   20096      // 157 * 128, padded
#define K2     512        // GEMM K = 2*D

// ---------------- scratch (__device__ globals; zero-init, no allocs) -------
__device__ __align__(128) __half g_Ah[(size_t)MAXN * K2];  // [row, 512] fp16
__device__ __align__(128) __half g_Bh[D * K2];             // [n, 512] fp16 (W^T)
__device__ float g_vs[D];
__device__ float g_vn[D];

__device__ __forceinline__ uint32_t smem_u32(const void* p) {
    uint32_t a;
    asm("{ .reg .u64 t; cvta.to.shared.u64 t, %1; cvt.u32.u64 %0, t; }" : "=r"(a) : "l"(p));
    return a;
}

// ---------------------------------------------------------------------------
// prep: blocks 0..15 -> v = W @ a GEMV; blocks 16..527 -> convB fp16.
// ---------------------------------------------------------------------------
__global__ void __launch_bounds__(256)
prep_kernel(const float* __restrict__ sw, const float* __restrict__ nw,
            const float* __restrict__ attn)
{
    const int b = blockIdx.x;
    const int t = threadIdx.x;

    if (b < 16) {
        __shared__ float a[D];
        const int wid = t >> 5, lane = t & 31;
        a[t] = attn[t];
        __syncthreads();

        const float* w = ((b & 1) == 0) ? sw : nw;
#pragma unroll
        for (int r = 0; r < 4; r++) {
            int row = (b >> 1) * 32 + wid * 4 + r;
            const float4* wr = (const float4*)(w + (size_t)row * D);
            float4 v0 = wr[lane], v1 = wr[lane + 32];
            float p = v0.x * a[4 * lane + 0] + v0.y * a[4 * lane + 1]
                    + v0.z * a[4 * lane + 2] + v0.w * a[4 * lane + 3]
                    + v1.x * a[128 + 4 * lane + 0] + v1.y * a[128 + 4 * lane + 1]
                    + v1.z * a[128 + 4 * lane + 2] + v1.w * a[128 + 4 * lane + 3];
#pragma unroll
            for (int o = 16; o > 0; o >>= 1) p += __shfl_down_sync(0xffffffffu, p, o);
            if (lane == 0) { if ((b & 1) == 0) g_vs[row] = p; else g_vn[row] = p; }
        }
    } else {
        int idx = (b - 16) * 256 + t;                // 0 .. 131071
        int n = idx & 255;
        int k = idx >> 8;                            // 0 .. 511
        float w = (k < D) ? sw[(size_t)k * D + n] : nw[(size_t)(k - D) * D + n];
        g_Bh[(size_t)n * K2 + k] = __float2half_rn(w);
    }
}

// ---------------------------------------------------------------------------
// Phase 1 (exact R9 form): per node — logits, softmax over 33, top-16,
// weighted neighbor sum. cp.async tile load overlapped with self-row work.
// ---------------------------------------------------------------------------
__global__ void __launch_bounds__(256)
phase1_kernel(const float* __restrict__ self_vecs,
              const float* __restrict__ neigh_vecs)
{
    __shared__ float4 tile[KNBR * D / 4];   // 32 KB
    __shared__ float4 vn4[D / 4];
    __shared__ float  dots[KNBR];
    __shared__ float  warp_part[8];
    __shared__ float  s_selflogit;
    __shared__ float  sel_w[TOPK];
    __shared__ int    sel_i[TOPK];

    const int n    = blockIdx.x;
    const int t    = threadIdx.x;
    const int wid  = t >> 5;
    const int lane = t & 31;

    const float4* src = (const float4*)(neigh_vecs + (size_t)n * KNBR * D);
#pragma unroll
    for (int i = 0; i < 8; i++) {
        uint32_t dst = smem_u32(&tile[t + 256 * i]);
        asm volatile("cp.async.cg.shared.global [%0], [%1], 16;"
                     :: "r"(dst), "l"((const void*)(src + t + 256 * i)));
    }
    asm volatile("cp.async.commit_group;");

    if (t < D / 4) vn4[t] = ((const float4*)g_vn)[t];

    float sv = self_vecs[(size_t)n * D + t];
    g_Ah[(size_t)n * K2 + t] = __float2half_rn(sv);
    float sp = sv * g_vs[t];
#pragma unroll
    for (int o = 16; o > 0; o >>= 1) sp += __shfl_down_sync(0xffffffffu, sp, o);
    if (lane == 0) warp_part[wid] = sp;

    asm volatile("cp.async.wait_group 0;");
    __syncthreads();

#pragma unroll
    for (int r = 0; r < 4; r++) {
        int row = wid * 4 + r;
        float4 a0 = tile[row * 64 + lane];
        float4 a1 = tile[row * 64 + 32 + lane];
        float4 b0 = vn4[lane];
        float4 b1 = vn4[32 + lane];
        float p = a0.x * b0.x + a0.y * b0.y + a0.z * b0.z + a0.w * b0.w
                + a1.x * b1.x + a1.y * b1.y + a1.z * b1.z + a1.w * b1.w;
#pragma unroll
        for (int o = 16; o > 0; o >>= 1) p += __shfl_down_sync(0xffffffffu, p, o);
        if (lane == 0) dots[row] = p;
    }
    if (t == 0) {
        float s = 0.f;
#pragma unroll
        for (int i = 0; i < 8; i++) s += warp_part[i];
        s_selflogit = s;
    }
    __syncthreads();

    if (wid == 0) {
        float l  = fmaxf(dots[lane], 0.f);
        float l0 = fmaxf(s_selflogit, 0.f);
        float m = l;
#pragma unroll
        for (int o = 16; o > 0; o >>= 1) m = fmaxf(m, __shfl_xor_sync(0xffffffffu, m, o));
        m = fmaxf(m, l0);
        float e = expf(l - m);
        float ssum = e;
#pragma unroll
        for (int o = 16; o > 0; o >>= 1) ssum += __shfl_xor_sync(0xffffffffu, ssum, o);
        float denom = ssum + expf(l0 - m);
        float score = e / denom;

        int rank = 0;
#pragma unroll
        for (int j = 0; j < KNBR; j++) {
            float sj = __shfl_sync(0xffffffffu, score, j);
            rank += (sj > score) || (sj == score && j < lane);
        }
        if (rank < TOPK) { sel_w[rank] = score; sel_i[rank] = lane; }
    }
    __syncthreads();

    const float* ts = (const float*)tile;
    float acc = 0.f;
#pragma unroll
    for (int i = 0; i < TOPK; i++) acc += sel_w[i] * ts[sel_i[i] * D + t];
    g_Ah[(size_t)n * K2 + D + t] = __float2half_rn(acc);
}

// ---------------------------------------------------------------------------
// Phase 2: out = relu(A @ B^T), single-pass fp16, fp32 accum.
// BM=128, BN=128, BK=64, 8 warps (64x32 warp tiles), 3-stage cp.async.
// NEW vs R9: register-fragment double buffering across the 4 k16 steps
// (load s+1's fragments while computing s) to overlap LDS latency with MMA.
// ---------------------------------------------------------------------------
#define BK    64
#define STG   36864                    // stage bytes: A 18432 + B 18432
#define AOF   0
#define B0OF  18432
#define GEMM_SMEM (3 * STG)            // 110592
#define NIT   8

__global__ void __launch_bounds__(256, 2)
gemm_kernel(float* __restrict__ out, int nrows)
{
    extern __shared__ uint8_t sm[];
    const uint32_t smb = smem_u32(sm);

    const int t    = threadIdx.x;
    const int wid  = t >> 5;
    const int lane = t & 31;
    const int row0 = blockIdx.x * 128;
    const int col0 = blockIdx.y * 128;
    const int wm   = (wid >> 2) * 64;    // 0/64
    const int wn   = (wid & 3) * 32;     // 0/32/64/96

    uint32_t offA[4];
#pragma unroll
    for (int i = 0; i < 4; i++)
        offA[i] = AOF + (uint32_t)(wm + i * 16 + (lane & 15)) * 144
                + (uint32_t)(((lane >> 4) << 3) * 2);
    uint32_t offB[2];
#pragma unroll
    for (int p = 0; p < 2; p++)
        offB[p] = (uint32_t)(wn + (2 * p + ((lane >> 3) >> 1)) * 8 + (lane & 7)) * 144
                + (uint32_t)(((lane >> 3) & 1) * 16);

    float acc[4][4][4];
#pragma unroll
    for (int i = 0; i < 4; i++)
#pragma unroll
        for (int j = 0; j < 4; j++)
#pragma unroll
            for (int q = 0; q < 4; q++) acc[i][j][q] = 0.f;

    auto prefetch = [&](int jt, int st) {
        const int koff = jt * BK;
        uint8_t* stage = sm + st * STG;
#pragma unroll
        for (int i = 0; i < 4; i++) {
            int idx = t + i * 256;
            int r = idx >> 3, c = idx & 7;
            uint32_t da = smem_u32(stage + AOF + r * 144 + c * 16);
            const void* sa = g_Ah + (size_t)(row0 + r) * K2 + koff + c * 8;
            asm volatile("cp.async.cg.shared.global [%0], [%1], 16;" :: "r"(da), "l"(sa));
        }
#pragma unroll
        for (int i = 0; i < 4; i++) {
            int idx = t + i * 256;
            int r = idx >> 3, c = idx & 7;
            uint32_t db = smem_u32(stage + B0OF + r * 144 + c * 16);
            const void* sb = g_Bh + (size_t)(col0 + r) * K2 + koff + c * 8;
            asm volatile("cp.async.cg.shared.global [%0], [%1], 16;" :: "r"(db), "l"(sb));
        }
        asm volatile("cp.async.commit_group;");
    };

    prefetch(0, 0);
    prefetch(1, 1);

    // double-buffered register fragments
    uint32_t a[2][4][4], b[2][4][2];

    auto ldfrag = [&](uint32_t sk, int pb) {
#pragma unroll
        for (int i = 0; i < 4; i++) {
            asm volatile("ldmatrix.sync.aligned.m8n8.x4.shared.b16 {%0,%1,%2,%3}, [%4];"
                         : "=r"(a[pb][i][0]), "=r"(a[pb][i][1]),
                           "=r"(a[pb][i][2]), "=r"(a[pb][i][3])
                         : "r"(sk + offA[i]));
        }
#pragma unroll
        for (int p = 0; p < 2; p++) {
            asm volatile("ldmatrix.sync.aligned.m8n8.x4.shared.b16 {%0,%1,%2,%3}, [%4];"
                         : "=r"(b[pb][2 * p][0]), "=r"(b[pb][2 * p][1]),
                           "=r"(b[pb][2 * p + 1][0]), "=r"(b[pb][2 * p + 1][1])
                         : "r"(sk + B0OF + offB[p]));
        }
    };

#pragma unroll 1
    for (int it = 0; it < NIT; it++) {
        asm volatile("cp.async.wait_group 1;");
        __syncthreads();                 // it-1 compute done before stage reuse below

        if (it + 2 < NIT) prefetch(it + 2, (it + 2) % 3);
        else asm volatile("cp.async.commit_group;");

        const uint32_t stage = smb + (uint32_t)((it % 3) * STG);

        ldfrag(stage, 0);                // fragments for k16 step 0
#pragma unroll
        for (int s = 0; s < 4; s++) {    // four k16 steps in BK=64
            const int cur = s & 1;
            if (s < 3) ldfrag(stage + (uint32_t)((s + 1) * 32), cur ^ 1);
#pragma unroll
            for (int i = 0; i < 4; i++)
#pragma unroll
                for (int j = 0; j < 4; j++) {
                    asm volatile(
                        "mma.sync.aligned.m16n8k16.row.col.f32.f16.f16.f32 "
                        "{%0,%1,%2,%3}, {%4,%5,%6,%7}, {%8,%9}, {%0,%1,%2,%3};"
                        : "+f"(acc[i][j][0]), "+f"(acc[i][j][1]),
                          "+f"(acc[i][j][2]), "+f"(acc[i][j][3])
                        : "r"(a[cur][i][0]), "r"(a[cur][i][1]),
                          "r"(a[cur][i][2]), "r"(a[cur][i][3]),
                          "r"(b[cur][j][0]), "r"(b[cur][j][1]));
                }
        }
    }

    __syncthreads();

    // epilogue: relu + store
#pragma unroll
    for (int i = 0; i < 4; i++) {
        int rA = row0 + wm + i * 16 + (lane >> 2);
        int rB = rA + 8;
#pragma unroll
        for (int j = 0; j < 4; j++) {
            int c = col0 + wn + j * 8 + (lane & 3) * 2;
            if (rA < nrows) {
                float2 v;
                v.x = fmaxf(acc[i][j][0], 0.f);
                v.y = fmaxf(acc[i][j][1], 0.f);
                *(float2*)&out[(size_t)rA * D + c] = v;
            }
            if (rB < nrows) {
                float2 v;
                v.x = fmaxf(acc[i][j][2], 0.f);
                v.y = fmaxf(acc[i][j][3], 0.f);
                *(float2*)&out[(size_t)rB * D + c] = v;
            }
        }
    }
}

// ---------------------------------------------------------------------------
extern "C" void kernel_launch(void* const* d_in, const int* in_sizes, int n_in,
                              void* d_out, int out_size)
{
    const float* self_vecs = (const float*)d_in[0];
    const float* neigh     = (const float*)d_in[1];
    const float* sw        = (const float*)d_in[2];
    const float* nw        = (const float*)d_in[3];
    const float* attn      = (const float*)d_in[4];
    float* out             = (float*)d_out;

    const int nrows = in_sizes[0] / D;   // 20000

    prep_kernel<<<16 + (D * K2) / 256, 256>>>(sw, nw, attn);
    phase1_kernel<<<nrows, 256>>>(self_vecs, neigh);

    cudaFuncSetAttribute(gemm_kernel, cudaFuncAttributeMaxDynamicSharedMemorySize, GEMM_SMEM);
    dim3 g2((nrows + 127) / 128, 2);
    gemm_kernel<<<g2, 256, GEMM_SMEM>>>(out, nrows);
}